// round 3
// baseline (speedup 1.0000x reference)
#include <cuda_runtime.h>

// GRUModel: T=2048, B=64, IN=256, H=256.
// out[t,b,h] = (1-z)*n + z*hid  with gates from gi = x @ w_ih^T, gh = hid @ w_hh^T (hid fixed).
// Strategy: tiny gh kernel -> __device__ scratch; big fused GEMM (M=131072, K=256, N=3*256)
// with f32x2 packed FMA inner loop and fused sigmoid/tanh epilogue.

#define T_DIM 2048
#define B_DIM 64
#define IN_DIM 256
#define H_DIM 256
#define M_DIM (T_DIM * B_DIM)      // 131072
#define G3 (3 * H_DIM)             // 768

#define BM 128                      // rows per block
#define BH 32                       // h columns per block (x3 gates = 96 gemm cols)
#define KC 16                       // k chunk

__device__ float g_gh[B_DIM * G3];  // gh[b][g] includes b_hh

// ---------- small helpers ----------
__device__ __forceinline__ unsigned long long splat2(float v) {
    unsigned long long r;
    asm("mov.b64 %0, {%1, %1};" : "=l"(r) : "f"(v));
    return r;
}
__device__ __forceinline__ void ffma2(unsigned long long& d, unsigned long long a, unsigned long long b) {
    asm("fma.rn.f32x2 %0, %1, %2, %0;" : "+l"(d) : "l"(a), "l"(b));
}
__device__ __forceinline__ float2 unpack2(unsigned long long v) {
    float2 f;
    asm("mov.b64 {%0, %1}, %2;" : "=f"(f.x), "=f"(f.y) : "l"(v));
    return f;
}
__device__ __forceinline__ float sigmoidf_acc(float x) {
    return 1.0f / (1.0f + expf(-x));
}

// ---------- gh = hid @ w_hh^T + b_hh  (64 x 768, K=256) ----------
__global__ void gh_kernel(const float* __restrict__ hid,
                          const float* __restrict__ w_hh,
                          const float* __restrict__ b_hh) {
    int b = blockIdx.x;                     // 0..63
    int g = blockIdx.y * 256 + threadIdx.x; // 0..767
    __shared__ float hs[H_DIM];
    hs[threadIdx.x] = hid[b * H_DIM + threadIdx.x];
    __syncthreads();
    const float4* w = (const float4*)(w_hh + (size_t)g * H_DIM);
    float s = b_hh[g];
#pragma unroll 8
    for (int k4 = 0; k4 < H_DIM / 4; k4++) {
        float4 wv = w[k4];
        s += hs[k4 * 4 + 0] * wv.x;
        s += hs[k4 * 4 + 1] * wv.y;
        s += hs[k4 * 4 + 2] * wv.z;
        s += hs[k4 * 4 + 3] * wv.w;
    }
    g_gh[b * G3 + g] = s;
}

// ---------- main fused GEMM + gate epilogue ----------
// grid: (M/BM = 1024, H/BH = 8), block: 256 threads
// thread (tx in [0,16), ty in [0,16)): rows ty*8..ty*8+7 (as 4 packed pairs), h = h0 + tx*2 + {0,1}
__global__ __launch_bounds__(256, 2)
void gru_main(const float* __restrict__ x,
              const float* __restrict__ hid,
              const float* __restrict__ w_ih,
              const float* __restrict__ b_ih,
              float* __restrict__ out) {
    __shared__ float As[KC][BM + 4];       // transposed x tile; stride 132 floats (16B-aligned rows)
    __shared__ float Bs[3][KC][BH];        // weight tile per gate

    const int m0 = blockIdx.x * BM;
    const int h0 = blockIdx.y * BH;
    const int tid = threadIdx.x;
    const int tx = tid & 15;
    const int ty = tid >> 4;

    // acc[gate][row-pair][j] packed over 2 adjacent rows
    unsigned long long acc[3][4][2];
#pragma unroll
    for (int g = 0; g < 3; g++)
#pragma unroll
        for (int rp = 0; rp < 4; rp++) {
            acc[g][rp][0] = 0ull;
            acc[g][rp][1] = 0ull;
        }

    for (int k0 = 0; k0 < IN_DIM; k0 += KC) {
        // --- load A tile: 128 rows x 16 k = 512 float4, 2 per thread, transpose into As[k][row]
#pragma unroll
        for (int i = 0; i < 2; i++) {
            int idx = tid + i * 256;
            int row = idx >> 2, kq = idx & 3;
            float4 v = *(const float4*)(x + (size_t)(m0 + row) * IN_DIM + k0 + kq * 4);
            As[kq * 4 + 0][row] = v.x;
            As[kq * 4 + 1][row] = v.y;
            As[kq * 4 + 2][row] = v.z;
            As[kq * 4 + 3][row] = v.w;
        }
        // --- load B tile: 96 gemm-cols x 16 k = 384 float4
#pragma unroll
        for (int i = 0; i < 2; i++) {
            int idx = tid + i * 256;
            if (idx < 384) {
                int c = idx >> 2, kq = idx & 3;       // c in 0..95
                int g = c >> 5, h = c & 31;
                float4 v = *(const float4*)(w_ih + (size_t)(g * H_DIM + h0 + h) * IN_DIM + k0 + kq * 4);
                Bs[g][kq * 4 + 0][h] = v.x;
                Bs[g][kq * 4 + 1][h] = v.y;
                Bs[g][kq * 4 + 2][h] = v.z;
                Bs[g][kq * 4 + 3][h] = v.w;
            }
        }
        __syncthreads();

#pragma unroll
        for (int kk = 0; kk < KC; kk++) {
            // 8 rows as 4 packed pairs (contiguous in transposed As)
            ulonglong2 aLo = *(const ulonglong2*)&As[kk][ty * 8];
            ulonglong2 aHi = *(const ulonglong2*)&As[kk][ty * 8 + 4];
            unsigned long long ap[4] = {aLo.x, aLo.y, aHi.x, aHi.y};

            unsigned long long bb[3][2];
#pragma unroll
            for (int g = 0; g < 3; g++) {
                float2 bv = *(const float2*)&Bs[g][kk][tx * 2];
                bb[g][0] = splat2(bv.x);
                bb[g][1] = splat2(bv.y);
            }
#pragma unroll
            for (int g = 0; g < 3; g++)
#pragma unroll
                for (int rp = 0; rp < 4; rp++) {
                    ffma2(acc[g][rp][0], ap[rp], bb[g][0]);
                    ffma2(acc[g][rp][1], ap[rp], bb[g][1]);
                }
        }
        __syncthreads();
    }

    // ---------- epilogue ----------
    const int hbase = h0 + tx * 2;
    float bir[2], biz[2], bin_[2];
#pragma unroll
    for (int j = 0; j < 2; j++) {
        bir[j]  = b_ih[hbase + j];
        biz[j]  = b_ih[H_DIM + hbase + j];
        bin_[j] = b_ih[2 * H_DIM + hbase + j];
    }

#pragma unroll
    for (int rp = 0; rp < 4; rp++) {
        float2 vr[2], vz[2], vn[2];
#pragma unroll
        for (int j = 0; j < 2; j++) {
            vr[j] = unpack2(acc[0][rp][j]);
            vz[j] = unpack2(acc[1][rp][j]);
            vn[j] = unpack2(acc[2][rp][j]);
        }
#pragma unroll
        for (int half = 0; half < 2; half++) {
            int row = ty * 8 + rp * 2 + half;
            int m = m0 + row;
            int b = m & (B_DIM - 1);
            const float* ghb = g_gh + b * G3;
            float o[2];
#pragma unroll
            for (int j = 0; j < 2; j++) {
                int h = hbase + j;
                float ir = (half ? vr[j].y : vr[j].x) + bir[j];
                float iz = (half ? vz[j].y : vz[j].x) + biz[j];
                float in_ = (half ? vn[j].y : vn[j].x) + bin_[j];
                float r = sigmoidf_acc(ir + ghb[h]);
                float z = sigmoidf_acc(iz + ghb[H_DIM + h]);
                float n = tanhf(in_ + r * ghb[2 * H_DIM + h]);
                float hv = hid[b * H_DIM + h];
                o[j] = (1.0f - z) * n + z * hv;
            }
            *(float2*)&out[(size_t)m * H_DIM + hbase] = make_float2(o[0], o[1]);
            if (m >= M_DIM - B_DIM) {
                // duplicate out[-1] tail
                *(float2*)&out[(size_t)M_DIM * H_DIM + (size_t)b * H_DIM + hbase] =
                    make_float2(o[0], o[1]);
            }
        }
    }
}

extern "C" void kernel_launch(void* const* d_in, const int* in_sizes, int n_in,
                              void* d_out, int out_size) {
    const float* x    = (const float*)d_in[0];
    const float* hid  = (const float*)d_in[1];
    const float* w_ih = (const float*)d_in[2];
    const float* w_hh = (const float*)d_in[3];
    const float* b_ih = (const float*)d_in[4];
    const float* b_hh = (const float*)d_in[5];
    float* out = (float*)d_out;

    gh_kernel<<<dim3(B_DIM, 3), 256>>>(hid, w_hh, b_hh);
    gru_main<<<dim3(M_DIM / BM, H_DIM / BH), 256>>>(x, hid, w_ih, b_ih, out);
}

// round 9
// speedup vs baseline: 3.3794x; 3.3794x over previous
#include <cuda_runtime.h>
#include <cuda_fp16.h>
#include <cstdint>

// GRUModel: T=2048, B=64, IN=256, H=256.  hid never updates -> one big GEMM:
//   gi = x[131072,256] @ w_ih^T[256,768]   via mma.sync m16n8k16 fp16 (f32 accum)
//   gh = hid @ w_hh^T + b_hh (+ b_ih folded for r,z)  -> tiny fp32 kernel
// Gate epilogue fused, reading accumulators straight from registers.
// (tcgen05 is unusable here: harness compiles via compute_103 PTX target.)

#define B_DIM 64
#define IN_DIM 256
#define H_DIM 256
#define M_DIM 131072
#define G3 768

#define BM 128                 // M rows per CTA
#define NG 192                 // gemm cols per CTA = 64 h x 3 gates
#define KC 32                  // k per chunk
#define NCH (IN_DIM / KC)      // 8
#define ASTR 80                // padded row stride in bytes (32 fp16 + 8B pad)

#define SA 0
#define SB (BM * ASTR)                  // 10240
#define SBUF (SB + NG * ASTR)           // 25600
#define SM_TOTAL (2 * SBUF)             // 51200 (dynamic)

__device__ float g_gh[B_DIM * G3];      // gh + b_hh (+ b_ih for gates r,z)

// ---------------- helpers ----------------
__device__ __forceinline__ uint32_t smem_u32(const void* p) {
    uint32_t a;
    asm("{ .reg .u64 t; cvta.to.shared.u64 t, %1; cvt.u32.u64 %0, t; }" : "=r"(a) : "l"(p));
    return a;
}
__device__ __forceinline__ uint32_t f2h2(float a, float b) {
    __half2 h = __floats2half2_rn(a, b);
    return *reinterpret_cast<uint32_t*>(&h);
}
__device__ __forceinline__ void sts128(uint32_t a, uint32_t x0, uint32_t x1, uint32_t x2, uint32_t x3) {
    asm volatile("st.shared.v4.b32 [%0], {%1,%2,%3,%4};" :: "r"(a), "r"(x0), "r"(x1), "r"(x2), "r"(x3));
}
__device__ __forceinline__ void ldsm4(uint32_t& r0, uint32_t& r1, uint32_t& r2, uint32_t& r3, uint32_t a) {
    asm volatile("ldmatrix.sync.aligned.m8n8.x4.shared.b16 {%0,%1,%2,%3}, [%4];"
                 : "=r"(r0), "=r"(r1), "=r"(r2), "=r"(r3) : "r"(a));
}
__device__ __forceinline__ void mma16816(float* c, uint32_t a0, uint32_t a1, uint32_t a2, uint32_t a3,
                                         uint32_t b0, uint32_t b1) {
    asm volatile("mma.sync.aligned.m16n8k16.row.col.f32.f16.f16.f32 "
                 "{%0,%1,%2,%3}, {%4,%5,%6,%7}, {%8,%9}, {%0,%1,%2,%3};"
                 : "+f"(c[0]), "+f"(c[1]), "+f"(c[2]), "+f"(c[3])
                 : "r"(a0), "r"(a1), "r"(a2), "r"(a3), "r"(b0), "r"(b1));
}
__device__ __forceinline__ float tanh_fast(float x) {
    float y;
    asm("tanh.approx.f32 %0, %1;" : "=f"(y) : "f"(x));
    return y;
}
__device__ __forceinline__ float sig_fast(float x) {   // 0.5*tanh(0.5x)+0.5
    return fmaf(0.5f, tanh_fast(0.5f * x), 0.5f);
}
// gemm col c (0..191) within the CTA -> w_ih row: c = hg*24 + gate*8 + hl
__device__ __forceinline__ int wrow_of(int c, int h0) {
    int hg = c / 24, rm = c % 24;
    return (rm / 8) * H_DIM + h0 + hg * 8 + (rm % 8);
}

// ---------- gh = hid @ w_hh^T + b_hh (+ b_ih for r,z)  (64 x 768) ----------
__global__ void gh_kernel(const float* __restrict__ hid,
                          const float* __restrict__ w_hh,
                          const float* __restrict__ b_hh,
                          const float* __restrict__ b_ih) {
    int b = blockIdx.x;
    int g = blockIdx.y * 256 + threadIdx.x;
    __shared__ float hs[H_DIM];
    hs[threadIdx.x] = hid[b * H_DIM + threadIdx.x];
    __syncthreads();
    const float4* w = (const float4*)(w_hh + (size_t)g * H_DIM);
    float s = b_hh[g] + (g < 2 * H_DIM ? b_ih[g] : 0.0f);
#pragma unroll 8
    for (int k4 = 0; k4 < H_DIM / 4; k4++) {
        float4 wv = w[k4];
        s += hs[k4 * 4 + 0] * wv.x;
        s += hs[k4 * 4 + 1] * wv.y;
        s += hs[k4 * 4 + 2] * wv.z;
        s += hs[k4 * 4 + 3] * wv.w;
    }
    g_gh[b * G3 + g] = s;
}

// ---------- main GEMM (mma.sync fp16) + fused gate epilogue ----------
// grid (4, 1024): blockIdx.x = h-tile (64 h), blockIdx.y = m-tile (128 rows).
// 256 threads = 8 warps: wm = wid&1 (64 rows), wn = wid>>1 (48 cols).
// Gemm-col layout within CTA: c = hg*24 + gate*8 + hl  (hg in 0..7, hl in 0..7)
//   -> each n8 fragment is one gate at 8 consecutive h; a thread's fragments
//      ni = q*3 + gate share the same h for all 3 gates.
__global__ __launch_bounds__(256, 1)
void gru_mma(const float* __restrict__ x,
             const float* __restrict__ w_ih,
             const float* __restrict__ hid,
             const float* __restrict__ b_ih,
             float* __restrict__ out) {
    extern __shared__ char smem[];
    const uint32_t sb = smem_u32(smem);
    const int tid = threadIdx.x;
    const int wid = tid >> 5, lane = tid & 31;
    const int wm = wid & 1, wn = wid >> 1;
    const int m0 = blockIdx.y * BM;
    const int h0 = blockIdx.x * 64;

    // ---- global->smem staging assignments ----
    // A: 128 rows x 2 k-halves; thread t: row = t&127, khalf = t>>7
    const int arow = tid & 127, akh = tid >> 7;
    const float* aG = x + (size_t)(m0 + arow) * IN_DIM + akh * 16;
    const uint32_t aSo = (uint32_t)(SA + arow * ASTR + akh * 32);

    // B: 192 rows x 2 k-halves = 384 tasks; thread t: task t; threads 0..127 also task 256+t
    const int rB1 = tid % 192, kB1 = tid / 192;
    const int rB2 = 64 + tid;
    const bool hasB2 = (tid < 128);
    const float* bG1 = w_ih + (size_t)wrow_of(rB1, h0) * IN_DIM + kB1 * 16;
    const float* bG2 = w_ih + (size_t)wrow_of(hasB2 ? rB2 : 0, h0) * IN_DIM + 16;
    const uint32_t bSo1 = (uint32_t)(SB + rB1 * ASTR + kB1 * 32);
    const uint32_t bSo2 = (uint32_t)(SB + (hasB2 ? rB2 : 0) * ASTR + 32);

    // ---- ldmatrix per-thread base offsets (within a buffer) ----
    // A m16k16 tile: lanes 0-7:(m0-7,k0) 8-15:(m8-15,k0) 16-23:(m0-7,k8) 24-31:(m8-15,k8)
    const uint32_t aLd = (uint32_t)(SA + (wm * 64 + (lane & 15)) * ASTR + ((lane >> 4) & 1) * 16);
    // B n8k16 pair: lanes 0-7:(n0-7,k0) 8-15:(n0-7,k8) 16-23:(n8-15,k0) 24-31:(n8-15,k8)
    const uint32_t bLd = (uint32_t)(SB + (wn * 48 + (lane & 7) + ((lane >> 4) & 1) * 8) * ASTR
                                    + ((lane >> 3) & 1) * 16);

    float acc[4][6][4];
#pragma unroll
    for (int mi = 0; mi < 4; mi++)
#pragma unroll
        for (int ni = 0; ni < 6; ni++)
#pragma unroll
            for (int e = 0; e < 4; e++) acc[mi][ni][e] = 0.0f;

    float4 ra[4], rb1[4], rb2[4];
#define LDG_CHUNK(cc) do {                                                    \
    _Pragma("unroll") for (int j = 0; j < 4; j++)                             \
        ra[j] = *(const float4*)(aG + (cc) * KC + j * 4);                     \
    _Pragma("unroll") for (int j = 0; j < 4; j++)                             \
        rb1[j] = *(const float4*)(bG1 + (cc) * KC + j * 4);                   \
    if (hasB2) {                                                              \
        _Pragma("unroll") for (int j = 0; j < 4; j++)                         \
            rb2[j] = *(const float4*)(bG2 + (cc) * KC + j * 4);               \
    }                                                                         \
} while (0)

#define STS_CHUNK(bo) do {                                                    \
    sts128(sb + (bo) + aSo,      f2h2(ra[0].x, ra[0].y), f2h2(ra[0].z, ra[0].w), \
                                 f2h2(ra[1].x, ra[1].y), f2h2(ra[1].z, ra[1].w)); \
    sts128(sb + (bo) + aSo + 16, f2h2(ra[2].x, ra[2].y), f2h2(ra[2].z, ra[2].w), \
                                 f2h2(ra[3].x, ra[3].y), f2h2(ra[3].z, ra[3].w)); \
    sts128(sb + (bo) + bSo1,      f2h2(rb1[0].x, rb1[0].y), f2h2(rb1[0].z, rb1[0].w), \
                                  f2h2(rb1[1].x, rb1[1].y), f2h2(rb1[1].z, rb1[1].w)); \
    sts128(sb + (bo) + bSo1 + 16, f2h2(rb1[2].x, rb1[2].y), f2h2(rb1[2].z, rb1[2].w), \
                                  f2h2(rb1[3].x, rb1[3].y), f2h2(rb1[3].z, rb1[3].w)); \
    if (hasB2) {                                                              \
        sts128(sb + (bo) + bSo2,      f2h2(rb2[0].x, rb2[0].y), f2h2(rb2[0].z, rb2[0].w), \
                                      f2h2(rb2[1].x, rb2[1].y), f2h2(rb2[1].z, rb2[1].w)); \
        sts128(sb + (bo) + bSo2 + 16, f2h2(rb2[2].x, rb2[2].y), f2h2(rb2[2].z, rb2[2].w), \
                                      f2h2(rb2[3].x, rb2[3].y), f2h2(rb2[3].z, rb2[3].w)); \
    }                                                                         \
} while (0)

    LDG_CHUNK(0);
    STS_CHUNK(0);
    __syncthreads();

#pragma unroll
    for (int c = 0; c < NCH; c++) {
        const uint32_t bo = (uint32_t)((c & 1) * SBUF);
        if (c + 1 < NCH) LDG_CHUNK(c + 1);       // overlaps the mma below
#pragma unroll
        for (int ks = 0; ks < 2; ks++) {
            uint32_t af[4][4], bf[3][4];
#pragma unroll
            for (int mi = 0; mi < 4; mi++)
                ldsm4(af[mi][0], af[mi][1], af[mi][2], af[mi][3],
                      sb + bo + aLd + mi * (16 * ASTR) + ks * 32);
#pragma unroll
            for (int n2 = 0; n2 < 3; n2++)
                ldsm4(bf[n2][0], bf[n2][1], bf[n2][2], bf[n2][3],
                      sb + bo + bLd + n2 * (16 * ASTR) + ks * 32);
#pragma unroll
            for (int mi = 0; mi < 4; mi++)
#pragma unroll
                for (int n2 = 0; n2 < 3; n2++) {
                    mma16816(acc[mi][n2 * 2 + 0], af[mi][0], af[mi][1], af[mi][2], af[mi][3],
                             bf[n2][0], bf[n2][1]);
                    mma16816(acc[mi][n2 * 2 + 1], af[mi][0], af[mi][1], af[mi][2], af[mi][3],
                             bf[n2][2], bf[n2][3]);
                }
        }
        if (c + 1 < NCH) {
            STS_CHUNK((uint32_t)(((c + 1) & 1) * SBUF));
            __syncthreads();
        }
    }

    // ---- epilogue: thread owns rows (gr, gr+8) per mi, and r/z/n at same h ----
    const int gr = lane >> 2, tg = lane & 3;
#pragma unroll
    for (int mi = 0; mi < 4; mi++) {
#pragma unroll
        for (int half = 0; half < 2; half++) {
            const int m = m0 + wm * 64 + mi * 16 + gr + half * 8;
            const int b = m & (B_DIM - 1);
            const float* ghb = g_gh + b * G3;
            const float* hvp = hid + b * H_DIM;
            const bool tail = (m >= M_DIM - B_DIM);
#pragma unroll
            for (int q = 0; q < 2; q++) {
                const int hb = h0 + (wn * 2 + q) * 8 + tg * 2;
                float2 o;
#pragma unroll
                for (int j = 0; j < 2; j++) {
                    const int h = hb + j;
                    const int e = half * 2 + j;
                    float r = sig_fast(acc[mi][q * 3 + 0][e] + ghb[h]);
                    float z = sig_fast(acc[mi][q * 3 + 1][e] + ghb[H_DIM + h]);
                    float n = tanh_fast(fmaf(r, ghb[2 * H_DIM + h],
                                             acc[mi][q * 3 + 2][e] + __ldg(&b_ih[2 * H_DIM + h])));
                    float hv = hvp[h];
                    float ov = n + z * (hv - n);
                    if (j) o.y = ov; else o.x = ov;
                }
                *(float2*)&out[(size_t)m * H_DIM + hb] = o;
                if (tail)
                    *(float2*)&out[(size_t)M_DIM * H_DIM + (size_t)b * H_DIM + hb] = o;
            }
        }
    }
}

extern "C" void kernel_launch(void* const* d_in, const int* in_sizes, int n_in,
                              void* d_out, int out_size) {
    const float* x    = (const float*)d_in[0];
    const float* hid  = (const float*)d_in[1];
    const float* w_ih = (const float*)d_in[2];
    const float* w_hh = (const float*)d_in[3];
    const float* b_ih = (const float*)d_in[4];
    const float* b_hh = (const float*)d_in[5];
    float* out = (float*)d_out;

    cudaFuncSetAttribute(gru_mma, cudaFuncAttributeMaxDynamicSharedMemorySize, SM_TOTAL);

    gh_kernel<<<dim3(B_DIM, 3), 256>>>(hid, w_hh, b_hh, b_ih);
    gru_mma<<<dim3(4, M_DIM / BM), 256, SM_TOTAL>>>(x, w_ih, hid, b_ih, out);
}

// round 12
// speedup vs baseline: 5.1962x; 1.5376x over previous
#include <cuda_runtime.h>
#include <cuda_fp16.h>
#include <cstdint>

// GRUModel: T=2048, B=64, IN=256, H=256.  hid never updates -> one big GEMM:
//   gi = x[131072,256] @ w_ih^T[256,768]   via mma.sync m16n8k16 fp16 (f32 accum)
// R10/R12: pre-convert x,w to fp16 in gmem; cp.async fp16 staging (4-stage ring),
//      B tile resident in smem; no conversion / register staging in hot loop.

#define B_DIM 64
#define IN_DIM 256
#define H_DIM 256
#define M_DIM 131072
#define G3 768

#define BM 128                 // M rows per CTA
#define NG 192                 // gemm cols per CTA = 64 h x 3 gates
#define KC 32                  // k per chunk
#define NCH (IN_DIM / KC)      // 8
#define NSTAGE 4

#define ASTR 80                // A stage row stride bytes (64 data + 16 pad)
#define BSTR 528               // B row stride bytes (512 data + 16 pad)
#define A_STAGE_BYTES (BM * ASTR)          // 10240
#define SB_OFF (NSTAGE * A_STAGE_BYTES)    // 40960
#define SM_TOTAL (SB_OFF + NG * BSTR)      // 142336

__device__ float  g_gh[B_DIM * G3];             // gh + b_hh (+ b_ih for r,z)
__device__ __half g_xh[(size_t)M_DIM * IN_DIM]; // x in fp16 (67 MB)
__device__ __half g_wh[4 * NG * IN_DIM];        // w_ih fp16, pre-permuted per h-tile

// ---------------- helpers ----------------
__device__ __forceinline__ uint32_t smem_u32(const void* p) {
    uint32_t a;
    asm("{ .reg .u64 t; cvta.to.shared.u64 t, %1; cvt.u32.u64 %0, t; }" : "=r"(a) : "l"(p));
    return a;
}
__device__ __forceinline__ uint32_t f2h2(float a, float b) {
    __half2 h = __floats2half2_rn(a, b);
    return *reinterpret_cast<uint32_t*>(&h);
}
__device__ __forceinline__ void ldsm4(uint32_t& r0, uint32_t& r1, uint32_t& r2, uint32_t& r3, uint32_t a) {
    asm volatile("ldmatrix.sync.aligned.m8n8.x4.shared.b16 {%0,%1,%2,%3}, [%4];"
                 : "=r"(r0), "=r"(r1), "=r"(r2), "=r"(r3) : "r"(a));
}
__device__ __forceinline__ void mma16816(float* c, uint32_t a0, uint32_t a1, uint32_t a2, uint32_t a3,
                                         uint32_t b0, uint32_t b1) {
    asm volatile("mma.sync.aligned.m16n8k16.row.col.f32.f16.f16.f32 "
                 "{%0,%1,%2,%3}, {%4,%5,%6,%7}, {%8,%9}, {%0,%1,%2,%3};"
                 : "+f"(c[0]), "+f"(c[1]), "+f"(c[2]), "+f"(c[3])
                 : "r"(a0), "r"(a1), "r"(a2), "r"(a3), "r"(b0), "r"(b1));
}
__device__ __forceinline__ float tanh_fast(float x) {
    float y;
    asm("tanh.approx.f32 %0, %1;" : "=f"(y) : "f"(x));
    return y;
}
__device__ __forceinline__ float sig_fast(float x) {
    return fmaf(0.5f, tanh_fast(0.5f * x), 0.5f);
}
__device__ __forceinline__ int wrow_of(int c, int h0) {   // c = hg*24 + gate*8 + hl
    int hg = c / 24, rm = c % 24;
    return (rm / 8) * H_DIM + h0 + hg * 8 + (rm % 8);
}
#define CP16(dst, src) asm volatile("cp.async.cg.shared.global [%0], [%1], 16;" :: "r"(dst), "l"(src))
#define CP_COMMIT()    asm volatile("cp.async.commit_group;" ::: "memory")
#define CP_WAIT2()     asm volatile("cp.async.wait_group 2;" ::: "memory")

// ---------- pre-pass: x -> fp16 ----------
__global__ __launch_bounds__(256) void conv_x(const float* __restrict__ x) {
    size_t g = (size_t)blockIdx.x * 256 + threadIdx.x;   // 4194304 threads, 8 floats each
    const float4* p = (const float4*)(x + g * 8);
    float4 a = p[0], b = p[1];
    uint4 o = make_uint4(f2h2(a.x, a.y), f2h2(a.z, a.w), f2h2(b.x, b.y), f2h2(b.z, b.w));
    *(uint4*)(g_xh + g * 8) = o;
}

// ---------- pre-pass: w_ih -> fp16, permuted to [ht][c][k] ----------
__global__ void conv_w(const float* __restrict__ w_ih) {
    int bx = blockIdx.x;                 // 0..767 = ht*192 + c
    int ht = bx / NG, c = bx % NG;
    int row = wrow_of(c, ht * 64);
    int t = threadIdx.x;                 // 64 threads x 4 k
    float4 v = *(const float4*)(w_ih + (size_t)row * IN_DIM + t * 4);
    *(uint2*)(g_wh + (size_t)bx * IN_DIM + t * 4) = make_uint2(f2h2(v.x, v.y), f2h2(v.z, v.w));
}

// ---------- gh = hid @ w_hh^T + b_hh (+ b_ih for r,z) ----------
__global__ void gh_kernel(const float* __restrict__ hid,
                          const float* __restrict__ w_hh,
                          const float* __restrict__ b_hh,
                          const float* __restrict__ b_ih) {
    int b = blockIdx.x;
    int g = blockIdx.y * 256 + threadIdx.x;
    __shared__ float hs[H_DIM];
    hs[threadIdx.x] = hid[b * H_DIM + threadIdx.x];
    __syncthreads();
    const float4* w = (const float4*)(w_hh + (size_t)g * H_DIM);
    float s = b_hh[g] + (g < 2 * H_DIM ? b_ih[g] : 0.0f);
#pragma unroll 8
    for (int k4 = 0; k4 < H_DIM / 4; k4++) {
        float4 wv = w[k4];
        s += hs[k4 * 4 + 0] * wv.x;
        s += hs[k4 * 4 + 1] * wv.y;
        s += hs[k4 * 4 + 2] * wv.z;
        s += hs[k4 * 4 + 3] * wv.w;
    }
    g_gh[b * G3 + g] = s;
}

// ---------- main GEMM + fused gate epilogue ----------
// grid (4, 1024): bx = h-tile, by = m-tile. 8 warps: wm=wid&1 (64 rows), wn=wid>>1 (48 cols).
__global__ __launch_bounds__(256, 1)
void gru_mma(const float* __restrict__ hid,
             const float* __restrict__ b_ih,
             float* __restrict__ out) {
    extern __shared__ char smem[];
    const uint32_t sb = smem_u32(smem);
    const int tid = threadIdx.x;
    const int wid = tid >> 5, lane = tid & 31;
    const int wm = wid & 1, wn = wid >> 1;
    const int m0 = blockIdx.y * BM;
    const int ht = blockIdx.x;
    const int h0 = ht * 64;

    // ---- cp.async assignments ----
    // A stage: 128 rows x 64B; thread t: row = t>>1, 32B at part (t&1)
    const int arow = tid >> 1, apart = tid & 1;
    const __half* aG = g_xh + (size_t)(m0 + arow) * IN_DIM + apart * 16;
    const uint32_t aSo = (uint32_t)(arow * ASTR + apart * 32);

    // ---- ldmatrix bases ----
    const uint32_t aLd = (uint32_t)((wm * 64 + (lane & 15)) * ASTR + ((lane >> 4) & 1) * 16);
    const uint32_t bLd = (uint32_t)(SB_OFF + (wn * 48 + (lane & 7) + ((lane >> 4) & 1) * 8) * BSTR
                                    + ((lane >> 3) & 1) * 16);

    // ---- prologue: resident B copy (192 rows x 512B) ----
    {
        const __half* wbase = g_wh + (size_t)ht * NG * IN_DIM;
#pragma unroll
        for (int i = 0; i < 24; i++) {
            int idx = i * 256 + tid;
            int row = idx >> 5, seg = idx & 31;
            CP16(sb + SB_OFF + row * BSTR + seg * 16, wbase + (size_t)row * IN_DIM + seg * 8);
        }
        CP_COMMIT();
    }
    // ---- prologue: A stages 0..2 ----
#pragma unroll
    for (int s = 0; s < NSTAGE - 1; s++) {
        CP16(sb + s * A_STAGE_BYTES + aSo,      aG + s * KC);
        CP16(sb + s * A_STAGE_BYTES + aSo + 16, aG + s * KC + 8);
        CP_COMMIT();
    }
    CP_WAIT2();                 // B + A0 arrived
    __syncthreads();

    float acc[4][6][4];
#pragma unroll
    for (int mi = 0; mi < 4; mi++)
#pragma unroll
        for (int ni = 0; ni < 6; ni++)
#pragma unroll
            for (int e = 0; e < 4; e++) acc[mi][ni][e] = 0.0f;

#pragma unroll
    for (int c = 0; c < NCH; c++) {
        const uint32_t ao = (uint32_t)((c & (NSTAGE - 1)) * A_STAGE_BYTES);
        const uint32_t bk = (uint32_t)(c * 64);            // k byte offset into B rows
#pragma unroll
        for (int ks = 0; ks < 2; ks++) {
            uint32_t af[4][4], bf[3][4];
#pragma unroll
            for (int mi = 0; mi < 4; mi++)
                ldsm4(af[mi][0], af[mi][1], af[mi][2], af[mi][3],
                      sb + ao + aLd + mi * (16 * ASTR) + ks * 32);
#pragma unroll
            for (int n2 = 0; n2 < 3; n2++)
                ldsm4(bf[n2][0], bf[n2][1], bf[n2][2], bf[n2][3],
                      sb + bLd + n2 * (16 * BSTR) + bk + ks * 32);
#pragma unroll
            for (int mi = 0; mi < 4; mi++)
#pragma unroll
                for (int n2 = 0; n2 < 3; n2++) {
                    mma16816(acc[mi][n2 * 2 + 0], af[mi][0], af[mi][1], af[mi][2], af[mi][3],
                             bf[n2][0], bf[n2][1]);
                    mma16816(acc[mi][n2 * 2 + 1], af[mi][0], af[mi][1], af[mi][2], af[mi][3],
                             bf[n2][2], bf[n2][3]);
                }
        }
        if (c + NSTAGE - 1 < NCH) {
            const uint32_t so = (uint32_t)(((c + NSTAGE - 1) & (NSTAGE - 1)) * A_STAGE_BYTES);
            CP16(sb + so + aSo,      aG + (c + NSTAGE - 1) * KC);
            CP16(sb + so + aSo + 16, aG + (c + NSTAGE - 1) * KC + 8);
        }
        CP_COMMIT();            // always commit (keeps wait_group accounting exact)
        if (c + 1 < NCH) {
            CP_WAIT2();         // chunk c+1 arrived
            __syncthreads();
        }
    }

    // ---- epilogue: thread owns rows (gr, gr+8) per mi; r/z/n at same h ----
    const int gr = lane >> 2, tg = lane & 3;
#pragma unroll
    for (int mi = 0; mi < 4; mi++) {
#pragma unroll
        for (int half = 0; half < 2; half++) {
            const int m = m0 + wm * 64 + mi * 16 + gr + half * 8;
            const int b = m & (B_DIM - 1);
            const float* ghb = g_gh + b * G3;
            const float* hvp = hid + b * H_DIM;
            const bool tail = (m >= M_DIM - B_DIM);
#pragma unroll
            for (int q = 0; q < 2; q++) {
                const int hb = h0 + (wn * 2 + q) * 8 + tg * 2;
                float2 o;
#pragma unroll
                for (int j = 0; j < 2; j++) {
                    const int h = hb + j;
                    const int e = half * 2 + j;
                    float r = sig_fast(acc[mi][q * 3 + 0][e] + ghb[h]);
                    float z = sig_fast(acc[mi][q * 3 + 1][e] + ghb[H_DIM + h]);
                    float n = tanh_fast(fmaf(r, ghb[2 * H_DIM + h],
                                             acc[mi][q * 3 + 2][e] + __ldg(&b_ih[2 * H_DIM + h])));
                    float hv = hvp[h];
                    float ov = n + z * (hv - n);
                    if (j) o.y = ov; else o.x = ov;
                }
                *(float2*)&out[(size_t)m * H_DIM + hb] = o;
                if (tail)
                    *(float2*)&out[(size_t)M_DIM * H_DIM + (size_t)b * H_DIM + hb] = o;
            }
        }
    }
}

extern "C" void kernel_launch(void* const* d_in, const int* in_sizes, int n_in,
                              void* d_out, int out_size) {
    const float* x    = (const float*)d_in[0];
    const float* hid  = (const float*)d_in[1];
    const float* w_ih = (const float*)d_in[2];
    const float* w_hh = (const float*)d_in[3];
    const float* b_ih = (const float*)d_in[4];
    const float* b_hh = (const float*)d_in[5];
    float* out = (float*)d_out;

    cudaFuncSetAttribute(gru_mma, cudaFuncAttributeMaxDynamicSharedMemorySize, SM_TOTAL);

    conv_x<<<(M_DIM * IN_DIM) / (256 * 8), 256>>>(x);
    conv_w<<<4 * NG, 64>>>(w_ih);
    gh_kernel<<<dim3(B_DIM, 3), 256>>>(hid, w_hh, b_hh, b_ih);
    gru_mma<<<dim3(4, M_DIM / BM), 256, SM_TOTAL>>>(hid, b_ih, out);
}